// round 7
// baseline (speedup 1.0000x reference)
#include <cuda_runtime.h>
#include <cstdint>

// Fixed shapes: pooled/indices [4,64,32,32,32], out [4,64,64,64,64]
#define NCHAN 256
#define POOL_PER_CHAN 32768
#define S_TOTAL 262144.0f

// Per-channel slice partials (32 dp-slices per channel) + arrival counters.
__device__ float d_partial[NCHAN * 32];
__device__ int   d_count[NCHAN];

// ---------------------------------------------------------------------------
// Kernel 0 (primary, ~1us): zero the per-channel arrival counters.
// Triggers PDL completion at entry; the fused kernel grid-syncs before its
// first atomic, so counters are guaranteed zero by then.
// ---------------------------------------------------------------------------
__global__ void zero_counts() {
    cudaTriggerProgrammaticLaunchCompletion();
    d_count[threadIdx.x] = 0;
}

// ---------------------------------------------------------------------------
// Fused kernel (secondary, PDL): unpool + gate with in-kernel gating reduction.
//
// u (16-output index) layout: [bc(8) | d0(6) | ho(6) | wo16(2)]
// => d0 = blockIdx&63 and bc = blockIdx>>6 are uniform per block; each block
//    covers the full (ho, wo) plane of one (bc, d0) slice.
//
// Gating: blocks with even d0 own pooled slice dp=d0/2. Their even-ho threads
// collectively read that slice exactly once (hp=ho/2 in 0..31, wp in 0..31).
// Block-reduce of silu over those threads -> d_partial[bc*32+dp] (fixed slot),
// release-increment d_count[bc]. Every block spins until count==32, then sums
// the 32 partials in fixed order (deterministic) -> log_sigmoid -> gate.
// ---------------------------------------------------------------------------
__global__ __launch_bounds__(256) void fused_kernel(const float* __restrict__ pooled,
                                                    const int*   __restrict__ indices,
                                                    float*       __restrict__ out) {
    const unsigned bc = blockIdx.x >> 6;          // uniform
    const unsigned d0 = blockIdx.x & 63u;         // uniform

    const unsigned u  = blockIdx.x * 256u + threadIdx.x;
    const unsigned wo = (u & 3u) << 4;            // 0,16,32,48
    const unsigned ho = (u >> 2) & 63u;

    const unsigned pbase = bc * POOL_PER_CHAN + (d0 >> 1) * 1024u + (ho >> 1) * 32u + (wo >> 1);

    // Front-issue all loads (independent of the zeroing kernel).
    const int4   ia = __ldg(reinterpret_cast<const int4*>(indices + pbase));
    const int4   ib = __ldg(reinterpret_cast<const int4*>(indices + pbase + 4));
    const float4 pa = __ldg(reinterpret_cast<const float4*>(pooled + pbase));
    const float4 pb = __ldg(reinterpret_cast<const float4*>(pooled + pbase + 4));

    // Counters are zero beyond this point (zero_counts grid completed).
    cudaGridDependencySynchronize();

    __shared__ float red[8];
    __shared__ float gsh;

    // --- Gating contribution (even-d0 blocks only; uniform branch) ---
    if ((d0 & 1u) == 0u) {
        float s = 0.0f;
        if ((ho & 1u) == 0u) {                    // even-ho threads: slice read once
            s  = pa.x * (1.0f / (1.0f + __expf(-pa.x)));
            s += pa.y * (1.0f / (1.0f + __expf(-pa.y)));
            s += pa.z * (1.0f / (1.0f + __expf(-pa.z)));
            s += pa.w * (1.0f / (1.0f + __expf(-pa.w)));
            s += pb.x * (1.0f / (1.0f + __expf(-pb.x)));
            s += pb.y * (1.0f / (1.0f + __expf(-pb.y)));
            s += pb.z * (1.0f / (1.0f + __expf(-pb.z)));
            s += pb.w * (1.0f / (1.0f + __expf(-pb.w)));
        }
        #pragma unroll
        for (int off = 16; off > 0; off >>= 1)
            s += __shfl_xor_sync(0xFFFFFFFFu, s, off);
        const int lane = threadIdx.x & 31;
        const int wid  = threadIdx.x >> 5;
        if (lane == 0) red[wid] = s;
        __syncthreads();
        if (threadIdx.x == 0) {
            float t = red[0];
            #pragma unroll
            for (int j = 1; j < 8; j++) t += red[j];
            d_partial[bc * 32u + (d0 >> 1)] = t;
            __threadfence();                      // release
            atomicAdd(&d_count[bc], 1);
        }
    }

    // --- Wait for all 32 slice partials of this channel, finalize gating ---
    if (threadIdx.x == 0) {
        volatile int* cnt = d_count + bc;
        while (*cnt < 32) { __nanosleep(64); }
        __threadfence();                          // acquire
        const float* pp = d_partial + bc * 32u;
        float t = 0.0f;
        #pragma unroll
        for (int j = 0; j < 32; j++) t += pp[j];  // fixed order: deterministic
        float m = t / S_TOTAL;
        gsh = fminf(m, 0.0f) - log1pf(__expf(-fabsf(m)));   // log_sigmoid(m)
    }
    __syncthreads();
    const float g = gsh;

    // --- Dense gated unpool: 16 outputs, two 256-bit stores ---
    const int base = (int)((d0 * 64u + ho) * 64u + wo);

    const float a0 = pa.x * g, a1 = pa.y * g, a2 = pa.z * g, a3 = pa.w * g;
    const float b0 = pb.x * g, b1 = pb.y * g, b2 = pb.z * g, b3 = pb.w * g;

    float o0  = (ia.x == base +  0) ? a0 : 0.0f;
    float o1  = (ia.x == base +  1) ? a0 : 0.0f;
    float o2  = (ia.y == base +  2) ? a1 : 0.0f;
    float o3  = (ia.y == base +  3) ? a1 : 0.0f;
    float o4  = (ia.z == base +  4) ? a2 : 0.0f;
    float o5  = (ia.z == base +  5) ? a2 : 0.0f;
    float o6  = (ia.w == base +  6) ? a3 : 0.0f;
    float o7  = (ia.w == base +  7) ? a3 : 0.0f;
    float o8  = (ib.x == base +  8) ? b0 : 0.0f;
    float o9  = (ib.x == base +  9) ? b0 : 0.0f;
    float o10 = (ib.y == base + 10) ? b1 : 0.0f;
    float o11 = (ib.y == base + 11) ? b1 : 0.0f;
    float o12 = (ib.z == base + 12) ? b2 : 0.0f;
    float o13 = (ib.z == base + 13) ? b2 : 0.0f;
    float o14 = (ib.w == base + 14) ? b3 : 0.0f;
    float o15 = (ib.w == base + 15) ? b3 : 0.0f;

    float* optr = out + 16ull * u;                // 64B-aligned
    asm volatile(
        "st.global.v8.f32 [%0], {%1, %2, %3, %4, %5, %6, %7, %8};"
        :: "l"(optr),
           "f"(o0), "f"(o1), "f"(o2), "f"(o3),
           "f"(o4), "f"(o5), "f"(o6), "f"(o7)
        : "memory");
    asm volatile(
        "st.global.v8.f32 [%0], {%1, %2, %3, %4, %5, %6, %7, %8};"
        :: "l"(optr + 8),
           "f"(o8),  "f"(o9),  "f"(o10), "f"(o11),
           "f"(o12), "f"(o13), "f"(o14), "f"(o15)
        : "memory");
}

// ---------------------------------------------------------------------------
extern "C" void kernel_launch(void* const* d_in, const int* in_sizes, int n_in,
                              void* d_out, int out_size) {
    const float* pooled  = (const float*)d_in[0];
    const int*   indices = (const int*)d_in[1];
    float*       out     = (float*)d_out;

    zero_counts<<<1, NCHAN>>>();

    cudaLaunchConfig_t cfg = {};
    cfg.gridDim  = dim3(16384, 1, 1);
    cfg.blockDim = dim3(256, 1, 1);
    cfg.dynamicSmemBytes = 0;
    cfg.stream = 0;
    cudaLaunchAttribute attr[1];
    attr[0].id = cudaLaunchAttributeProgrammaticStreamSerialization;
    attr[0].val.programmaticStreamSerializationAllowed = 1;
    cfg.attrs = attr;
    cfg.numAttrs = 1;
    cudaLaunchKernelEx(&cfg, fused_kernel, pooled, indices, out);
}

// round 9
// speedup vs baseline: 1.5252x; 1.5252x over previous
#include <cuda_runtime.h>
#include <cstdint>

// Fixed shapes: pooled/indices [4,64,32,32,32], out [4,64,64,64,64]
#define NCHAN 256
#define POOL_PER_CHAN 32768
#define SLOTS 4                      // partials per channel (1024 blocks = 1 wave)
#define S_TOTAL 262144.0f

__device__ float d_partial[NCHAN * SLOTS];

// ---------------------------------------------------------------------------
// Kernel 1 (primary): partial sum(silu(pooled)).
// 1024 blocks x 256 thr = ONE wave -> every CTA launches at t~0 and executes
// the PLC trigger immediately, so the PSS secondary can start launching right
// away (this was the R6 limiter: 2048 blocks = 2 waves).
// Each block reduces 8192 floats (8 float4 per thread).
// ---------------------------------------------------------------------------
__global__ __launch_bounds__(256) void gating_partial(const float* __restrict__ pooled) {
    cudaTriggerProgrammaticLaunchCompletion();

    const float4* __restrict__ p =
        reinterpret_cast<const float4*>(pooled) + (size_t)blockIdx.x * 2048;

    float s = 0.0f;
    #pragma unroll
    for (int i = 0; i < 8; i++) {
        float4 v = __ldg(&p[threadIdx.x + i * 256]);
        s += v.x * (1.0f / (1.0f + __expf(-v.x)));
        s += v.y * (1.0f / (1.0f + __expf(-v.y)));
        s += v.z * (1.0f / (1.0f + __expf(-v.z)));
        s += v.w * (1.0f / (1.0f + __expf(-v.w)));
    }

    #pragma unroll
    for (int off = 16; off > 0; off >>= 1)
        s += __shfl_xor_sync(0xFFFFFFFFu, s, off);

    __shared__ float sh[8];
    const int lane = threadIdx.x & 31;
    const int wid  = threadIdx.x >> 5;
    if (lane == 0) sh[wid] = s;
    __syncthreads();
    if (threadIdx.x == 0) {
        float t = sh[0];
        #pragma unroll
        for (int j = 1; j < 8; j++) t += sh[j];
        d_partial[blockIdx.x] = t;     // slot = bc*4 + sub (fixed, deterministic)
    }
}

// ---------------------------------------------------------------------------
// Kernel 2 (PSS secondary): dense unpool + gate. 16 outputs/thread, two
// 256-bit stores. Front-issues all loads, then grid-syncs on the gating grid
// (runtime-managed PDL wait — no custom sync), then finalizes log_sigmoid
// from the 4 fixed-order partials.
// u (16-output index) layout: [bc(8) | d0(6) | ho(6) | wo16(2)]
// ---------------------------------------------------------------------------
__global__ __launch_bounds__(256) void unpool_kernel(const float* __restrict__ pooled,
                                                     const int*   __restrict__ indices,
                                                     float*       __restrict__ out) {
    const unsigned bc = blockIdx.x >> 6;           // 64 blocks per channel

    const unsigned u  = blockIdx.x * 256u + threadIdx.x;
    const unsigned wo = (u & 3u) << 4;             // 0,16,32,48
    const unsigned ho = (u >> 2) & 63u;
    const unsigned d0 = (u >> 8) & 63u;

    const unsigned pbase = bc * POOL_PER_CHAN + (d0 >> 1) * 1024u + (ho >> 1) * 32u + (wo >> 1);

    // Front-issue all loads (independent of the gating grid).
    const int4   ia = __ldg(reinterpret_cast<const int4*>(indices + pbase));
    const int4   ib = __ldg(reinterpret_cast<const int4*>(indices + pbase + 4));
    const float4 pa = __ldg(reinterpret_cast<const float4*>(pooled + pbase));
    const float4 pb = __ldg(reinterpret_cast<const float4*>(pooled + pbase + 4));

    // Wait for gating grid completion (PDL dependency point).
    cudaGridDependencySynchronize();

    __shared__ float gsh;
    if (threadIdx.x == 0) {
        const float* pp = d_partial + bc * SLOTS;
        float t = pp[0] + pp[1] + pp[2] + pp[3];   // fixed order: deterministic
        float m = t / S_TOTAL;
        gsh = fminf(m, 0.0f) - log1pf(__expf(-fabsf(m)));   // log_sigmoid(m)
    }
    __syncthreads();
    const float g = gsh;

    const int base = (int)((d0 * 64u + ho) * 64u + wo);

    const float a0 = pa.x * g, a1 = pa.y * g, a2 = pa.z * g, a3 = pa.w * g;
    const float b0 = pb.x * g, b1 = pb.y * g, b2 = pb.z * g, b3 = pb.w * g;

    float o0  = (ia.x == base +  0) ? a0 : 0.0f;
    float o1  = (ia.x == base +  1) ? a0 : 0.0f;
    float o2  = (ia.y == base +  2) ? a1 : 0.0f;
    float o3  = (ia.y == base +  3) ? a1 : 0.0f;
    float o4  = (ia.z == base +  4) ? a2 : 0.0f;
    float o5  = (ia.z == base +  5) ? a2 : 0.0f;
    float o6  = (ia.w == base +  6) ? a3 : 0.0f;
    float o7  = (ia.w == base +  7) ? a3 : 0.0f;
    float o8  = (ib.x == base +  8) ? b0 : 0.0f;
    float o9  = (ib.x == base +  9) ? b0 : 0.0f;
    float o10 = (ib.y == base + 10) ? b1 : 0.0f;
    float o11 = (ib.y == base + 11) ? b1 : 0.0f;
    float o12 = (ib.z == base + 12) ? b2 : 0.0f;
    float o13 = (ib.z == base + 13) ? b2 : 0.0f;
    float o14 = (ib.w == base + 14) ? b3 : 0.0f;
    float o15 = (ib.w == base + 15) ? b3 : 0.0f;

    float* optr = out + 16ull * u;                 // 64B-aligned
    asm volatile(
        "st.global.v8.f32 [%0], {%1, %2, %3, %4, %5, %6, %7, %8};"
        :: "l"(optr),
           "f"(o0), "f"(o1), "f"(o2), "f"(o3),
           "f"(o4), "f"(o5), "f"(o6), "f"(o7)
        : "memory");
    asm volatile(
        "st.global.v8.f32 [%0], {%1, %2, %3, %4, %5, %6, %7, %8};"
        :: "l"(optr + 8),
           "f"(o8),  "f"(o9),  "f"(o10), "f"(o11),
           "f"(o12), "f"(o13), "f"(o14), "f"(o15)
        : "memory");
}

// ---------------------------------------------------------------------------
extern "C" void kernel_launch(void* const* d_in, const int* in_sizes, int n_in,
                              void* d_out, int out_size) {
    const float* pooled  = (const float*)d_in[0];
    const int*   indices = (const int*)d_in[1];
    float*       out     = (float*)d_out;

    gating_partial<<<NCHAN * SLOTS, 256>>>(pooled);          // 1024 blocks, 1 wave

    // Secondary launch with Programmatic Stream Serialization: begins
    // launching once all 1024 gating CTAs have executed the PLC trigger
    // (~immediately, since they are one wave).
    cudaLaunchConfig_t cfg = {};
    cfg.gridDim  = dim3(16384, 1, 1);
    cfg.blockDim = dim3(256, 1, 1);
    cfg.dynamicSmemBytes = 0;
    cfg.stream = 0;
    cudaLaunchAttribute attr[1];
    attr[0].id = cudaLaunchAttributeProgrammaticStreamSerialization;
    attr[0].val.programmaticStreamSerializationAllowed = 1;
    cfg.attrs = attr;
    cfg.numAttrs = 1;
    cudaLaunchKernelEx(&cfg, unpool_kernel, pooled, indices, out);
}

// round 11
// speedup vs baseline: 2.0172x; 1.3226x over previous
#include <cuda_runtime.h>
#include <cstdint>

// Fixed shapes: pooled/indices [4,64,32,32,32], out [4,64,64,64,64]
#define NCHAN 256
#define POOL_PER_CHAN 32768
#define SLOTS 8
#define S_TOTAL 262144.0f

__device__ float d_partial[NCHAN * SLOTS];

// ---------------------------------------------------------------------------
// Kernel 1 (primary): partial sum(silu(pooled)), 2048 blocks x 256 thr.
// Two 256-bit loads per thread (ld.global.nc.v8.f32), front-batched.
// PLC trigger at entry (PDL primary).
// ---------------------------------------------------------------------------
__global__ __launch_bounds__(256) void gating_partial(const float* __restrict__ pooled) {
    cudaTriggerProgrammaticLaunchCompletion();

    // Block owns 4096 consecutive floats: 256 threads x 16 floats.
    const float* p = pooled + (size_t)blockIdx.x * 4096 + threadIdx.x * 8;

    float v0, v1, v2, v3, v4, v5, v6, v7;
    float w0, w1, w2, w3, w4, w5, w6, w7;
    // Front-issue both 256-bit loads (second is +2048 floats = other half).
    asm volatile("ld.global.nc.v8.f32 {%0,%1,%2,%3,%4,%5,%6,%7}, [%8];"
                 : "=f"(v0), "=f"(v1), "=f"(v2), "=f"(v3),
                   "=f"(v4), "=f"(v5), "=f"(v6), "=f"(v7)
                 : "l"(p));
    asm volatile("ld.global.nc.v8.f32 {%0,%1,%2,%3,%4,%5,%6,%7}, [%8];"
                 : "=f"(w0), "=f"(w1), "=f"(w2), "=f"(w3),
                   "=f"(w4), "=f"(w5), "=f"(w6), "=f"(w7)
                 : "l"(p + 2048));

    float s = 0.0f;
    s += v0 * (1.0f / (1.0f + __expf(-v0)));
    s += v1 * (1.0f / (1.0f + __expf(-v1)));
    s += v2 * (1.0f / (1.0f + __expf(-v2)));
    s += v3 * (1.0f / (1.0f + __expf(-v3)));
    s += v4 * (1.0f / (1.0f + __expf(-v4)));
    s += v5 * (1.0f / (1.0f + __expf(-v5)));
    s += v6 * (1.0f / (1.0f + __expf(-v6)));
    s += v7 * (1.0f / (1.0f + __expf(-v7)));
    s += w0 * (1.0f / (1.0f + __expf(-w0)));
    s += w1 * (1.0f / (1.0f + __expf(-w1)));
    s += w2 * (1.0f / (1.0f + __expf(-w2)));
    s += w3 * (1.0f / (1.0f + __expf(-w3)));
    s += w4 * (1.0f / (1.0f + __expf(-w4)));
    s += w5 * (1.0f / (1.0f + __expf(-w5)));
    s += w6 * (1.0f / (1.0f + __expf(-w6)));
    s += w7 * (1.0f / (1.0f + __expf(-w7)));

    #pragma unroll
    for (int off = 16; off > 0; off >>= 1)
        s += __shfl_xor_sync(0xFFFFFFFFu, s, off);

    __shared__ float sh[8];
    const int lane = threadIdx.x & 31;
    const int wid  = threadIdx.x >> 5;
    if (lane == 0) sh[wid] = s;
    __syncthreads();
    if (threadIdx.x == 0) {
        float t = sh[0];
        #pragma unroll
        for (int j = 1; j < 8; j++) t += sh[j];
        d_partial[blockIdx.x] = t;     // slot = bc*8 + sub (fixed, deterministic)
    }
}

// ---------------------------------------------------------------------------
// Kernel 2 (PSS secondary): dense unpool + gate — UNCHANGED from the proven
// 50.1us version. 16 outputs/thread, two 256-bit stores. Front-issues loads,
// grid-syncs on gating, finalizes log_sigmoid from 8 fixed-order partials.
// u (16-output index) layout: [bc(8) | d0(6) | ho(6) | wo16(2)]
// ---------------------------------------------------------------------------
__global__ __launch_bounds__(256) void unpool_kernel(const float* __restrict__ pooled,
                                                     const int*   __restrict__ indices,
                                                     float*       __restrict__ out) {
    const unsigned bc = blockIdx.x >> 6;           // 64 blocks per channel

    const unsigned u  = blockIdx.x * 256u + threadIdx.x;
    const unsigned wo = (u & 3u) << 4;             // 0,16,32,48
    const unsigned ho = (u >> 2) & 63u;
    const unsigned d0 = (u >> 8) & 63u;

    const unsigned pbase = bc * POOL_PER_CHAN + (d0 >> 1) * 1024u + (ho >> 1) * 32u + (wo >> 1);

    // Front-issue all loads (independent of the gating grid).
    const int4   ia = __ldg(reinterpret_cast<const int4*>(indices + pbase));
    const int4   ib = __ldg(reinterpret_cast<const int4*>(indices + pbase + 4));
    const float4 pa = __ldg(reinterpret_cast<const float4*>(pooled + pbase));
    const float4 pb = __ldg(reinterpret_cast<const float4*>(pooled + pbase + 4));

    // Wait for gating grid completion (PDL dependency point).
    cudaGridDependencySynchronize();

    __shared__ float gsh;
    if (threadIdx.x == 0) {
        const float* pp = d_partial + bc * SLOTS;
        float t = 0.0f;
        #pragma unroll
        for (int j = 0; j < SLOTS; j++) t += pp[j];   // fixed order: deterministic
        float m = t / S_TOTAL;
        gsh = fminf(m, 0.0f) - log1pf(__expf(-fabsf(m)));   // log_sigmoid(m)
    }
    __syncthreads();
    const float g = gsh;

    const int base = (int)((d0 * 64u + ho) * 64u + wo);

    const float a0 = pa.x * g, a1 = pa.y * g, a2 = pa.z * g, a3 = pa.w * g;
    const float b0 = pb.x * g, b1 = pb.y * g, b2 = pb.z * g, b3 = pb.w * g;

    float o0  = (ia.x == base +  0) ? a0 : 0.0f;
    float o1  = (ia.x == base +  1) ? a0 : 0.0f;
    float o2  = (ia.y == base +  2) ? a1 : 0.0f;
    float o3  = (ia.y == base +  3) ? a1 : 0.0f;
    float o4  = (ia.z == base +  4) ? a2 : 0.0f;
    float o5  = (ia.z == base +  5) ? a2 : 0.0f;
    float o6  = (ia.w == base +  6) ? a3 : 0.0f;
    float o7  = (ia.w == base +  7) ? a3 : 0.0f;
    float o8  = (ib.x == base +  8) ? b0 : 0.0f;
    float o9  = (ib.x == base +  9) ? b0 : 0.0f;
    float o10 = (ib.y == base + 10) ? b1 : 0.0f;
    float o11 = (ib.y == base + 11) ? b1 : 0.0f;
    float o12 = (ib.z == base + 12) ? b2 : 0.0f;
    float o13 = (ib.z == base + 13) ? b2 : 0.0f;
    float o14 = (ib.w == base + 14) ? b3 : 0.0f;
    float o15 = (ib.w == base + 15) ? b3 : 0.0f;

    float* optr = out + 16ull * u;                 // 64B-aligned
    asm volatile(
        "st.global.v8.f32 [%0], {%1, %2, %3, %4, %5, %6, %7, %8};"
        :: "l"(optr),
           "f"(o0), "f"(o1), "f"(o2), "f"(o3),
           "f"(o4), "f"(o5), "f"(o6), "f"(o7)
        : "memory");
    asm volatile(
        "st.global.v8.f32 [%0], {%1, %2, %3, %4, %5, %6, %7, %8};"
        :: "l"(optr + 8),
           "f"(o8),  "f"(o9),  "f"(o10), "f"(o11),
           "f"(o12), "f"(o13), "f"(o14), "f"(o15)
        : "memory");
}

// ---------------------------------------------------------------------------
extern "C" void kernel_launch(void* const* d_in, const int* in_sizes, int n_in,
                              void* d_out, int out_size) {
    const float* pooled  = (const float*)d_in[0];
    const int*   indices = (const int*)d_in[1];
    float*       out     = (float*)d_out;

    gating_partial<<<NCHAN * SLOTS, 256>>>(pooled);          // 2048 blocks

    // Secondary launch with Programmatic Stream Serialization (the R6
    // structure that measured 60.0us total).
    cudaLaunchConfig_t cfg = {};
    cfg.gridDim  = dim3(16384, 1, 1);
    cfg.blockDim = dim3(256, 1, 1);
    cfg.dynamicSmemBytes = 0;
    cfg.stream = 0;
    cudaLaunchAttribute attr[1];
    attr[0].id = cudaLaunchAttributeProgrammaticStreamSerialization;
    attr[0].val.programmaticStreamSerializationAllowed = 1;
    cfg.attrs = attr;
    cfg.numAttrs = 1;
    cudaLaunchKernelEx(&cfg, unpool_kernel, pooled, indices, out);
}